// round 14
// baseline (speedup 1.0000x reference)
#include <cuda_runtime.h>

// ============================================================================
// GeneratorQuantumCircuit: 4-qubit state-vector sim, 1 thread = 1 batch elem.
// State = 16 complex amplitudes packed (re,im) as f32x2 in 64-bit registers.
//
// Tangent (deferred-cosine) gate algebra: every rotation applied as
// [[1,-t],[t,1]]; dropped cosine factors recovered by SELF-NORMALIZATION
// (unitary circuit => sum of probs = 1). RY gates: 2 fma2 per amplitude pair.
// CNOTs: register renames. Epilogue in packed f32x2 + one MUFU reciprocal.
//
// R13: in-kernel weight prep uses FAST-MATH tangents (__sincosf+__fdividef)
// instead of accurate tanf — R12's tanf slow-path code region inflated regs
// 39->48 and dropped occupancy 64->54%. Occupancy pinned via launch_bounds.
// ============================================================================

typedef unsigned long long u64;

// ---- packed f32x2 helpers (Blackwell sm_100+) ------------------------------

__device__ __forceinline__ u64 pk2(float lo, float hi) {
    u64 r; asm("mov.b64 %0, {%1, %2};" : "=l"(r) : "f"(lo), "f"(hi)); return r;
}
__device__ __forceinline__ void unpk2(u64 v, float& lo, float& hi) {
    asm("mov.b64 {%0, %1}, %2;" : "=f"(lo), "=f"(hi) : "l"(v));
}
__device__ __forceinline__ u64 mul2(u64 a, u64 b) {
    u64 r; asm("mul.rn.f32x2 %0, %1, %2;" : "=l"(r) : "l"(a), "l"(b)); return r;
}
__device__ __forceinline__ u64 add2(u64 a, u64 b) {
    u64 r; asm("add.rn.f32x2 %0, %1, %2;" : "=l"(r) : "l"(a), "l"(b)); return r;
}
__device__ __forceinline__ u64 fma2(u64 a, u64 b, u64 c) {
    u64 r; asm("fma.rn.f32x2 %0, %1, %2, %3;" : "=l"(r) : "l"(a), "l"(b), "l"(c)); return r;
}
__device__ __forceinline__ float hadd2(u64 v) {
    float lo, hi; unpk2(v, lo, hi); return lo + hi;
}

// fast tangent: MUFU sin/cos + MUFU-rcp divide; no slow-path code region
__device__ __forceinline__ float fast_tan_half(float x) {
    float s, c;
    __sincosf(0.5f * x, &s, &c);
    return __fdividef(s, c);
}

// CNOT(ctrl C, tgt T): pure register permutation when fully unrolled.
template <int C, int T>
__device__ __forceinline__ void cnot(u64* a) {
#pragma unroll
    for (int i = 0; i < 16; i++) {
        if ((i & (1 << C)) && !(i & (1 << T))) {
            u64 t = a[i];
            a[i] = a[i | (1 << T)];
            a[i | (1 << T)] = t;
        }
    }
}

__global__ void __launch_bounds__(256, 6)
qc_kernel(const float4* __restrict__ noise,
          const float*  __restrict__ weights,
          float4* __restrict__ out, int n) {
    __shared__ float wt_sh[8];

    // ---- per-block weight tangents: 8 fast-math tans, once per block -------
    if (threadIdx.x < 8) wt_sh[threadIdx.x] = fast_tan_half(weights[threadIdx.x]);
    __syncthreads();

    int b = blockIdx.x * blockDim.x + threadIdx.x;
    if (b >= n) return;

    float wt[8];
#pragma unroll
    for (int i = 0; i < 8; i++) wt[i] = wt_sh[i];   // LDS broadcast, N=1

    // ---- noise angles -> tangents (cosines never needed: self-normalizing) -
    float4 nz = noise[b];
    float t[4];
    t[0] = fast_tan_half(nz.x);
    t[1] = fast_tan_half(nz.y);
    t[2] = fast_tan_half(nz.z);
    t[3] = fast_tan_half(nz.w);

    // ---- product state (deferred cosines): amp(i) = prod_w (i_w ? -i*t : 1)
    // a[i] packed (re,im). a[i+h] = a[i] * (-i t) = (im*t, -re*t).
    u64 a[16];
    a[0] = pk2(1.0f, 0.0f);
#pragma unroll
    for (int w = 0; w < 4; w++) {
        const int h = 1 << w;
        u64 tn = pk2(t[w], -t[w]);
#pragma unroll
        for (int i = 0; i < (1 << w); i++) {
            float re, im;
            unpk2(a[i], re, im);
            a[i + h] = mul2(pk2(im, re), tn);
        }
    }

    // ---- 2 layers: CNOT ring + RY (deferred cosine: [[1,-t],[t,1]]) --------
#pragma unroll
    for (int layer = 0; layer < 2; layer++) {
        cnot<0, 1>(a);
        cnot<1, 2>(a);
        cnot<2, 3>(a);
        cnot<3, 0>(a);

#pragma unroll
        for (int w = 0; w < 4; w++) {
            float tw = wt[layer * 4 + w];
            u64 tp = pk2(tw, tw);
            u64 tn = pk2(-tw, -tw);
            const int h = 1 << w;
#pragma unroll
            for (int i = 0; i < 16; i++) {
                if (i & h) continue;
                u64 a0 = a[i], a1 = a[i | h];
                a[i]     = fma2(tn, a1, a0);  // a0 - t*a1  (re & im together)
                a[i | h] = fma2(tp, a0, a1);  // a1 + t*a0
            }
        }
    }

    // ---- packed squares + marginals, then normalize by total ---------------
    u64 q[16];
#pragma unroll
    for (int i = 0; i < 16; i++) q[i] = mul2(a[i], a[i]);  // (re^2, im^2)

    u64 s01 = add2(q[0],  q[1]),  s23 = add2(q[2],  q[3]);
    u64 s45 = add2(q[4],  q[5]),  s67 = add2(q[6],  q[7]);
    u64 s89 = add2(q[8],  q[9]),  sab = add2(q[10], q[11]);
    u64 scd = add2(q[12], q[13]), sef = add2(q[14], q[15]);

    u64 A = add2(s01, s23);   // q0..q3
    u64 B = add2(s45, s67);   // q4..q7
    u64 C = add2(s89, sab);   // q8..q11
    u64 D = add2(scd, sef);   // q12..q15

    // wire0: even indices
    u64 E = add2(add2(add2(q[0], q[2]), add2(q[4],  q[6])),
                 add2(add2(q[8], q[10]), add2(q[12], q[14])));
    // wire1: {0,1,4,5,8,9,12,13}
    u64 Y = add2(add2(s01, s45), add2(s89, scd));

    u64 AB = add2(A, B);                    // wire 3 numerator (and half of T)
    float T = hadd2(add2(AB, add2(C, D)));  // total probability mass
    float r = __frcp_rn(T);                 // MUFU reciprocal (pipe is idle)

    float4 o;
    o.x = r * hadd2(E);            // wire 0
    o.y = r * hadd2(Y);            // wire 1
    o.z = r * hadd2(add2(A, C));   // wire 2
    o.w = r * hadd2(AB);           // wire 3

    out[b] = o;
}

extern "C" void kernel_launch(void* const* d_in, const int* in_sizes, int n_in,
                              void* d_out, int out_size) {
    const float* noise   = (const float*)d_in[0];   // (B, 4) f32
    const float* weights = (const float*)d_in[1];   // (2, 4) f32
    int B = in_sizes[0] / 4;

    int threads = 256;
    int blocks = (B + threads - 1) / threads;
    qc_kernel<<<blocks, threads>>>((const float4*)noise, weights,
                                   (float4*)d_out, B);
}

// round 15
// speedup vs baseline: 1.0017x; 1.0017x over previous
#include <cuda_runtime.h>

// ============================================================================
// GeneratorQuantumCircuit: 4-qubit state-vector sim, 1 thread = 1 batch elem.
// State = 16 complex amplitudes packed (re,im) as f32x2 in 64-bit registers.
//
// Tangent (deferred-cosine) gate algebra: every rotation applied as
// [[1,-t],[t,1]]; dropped cosine factors recovered by SELF-NORMALIZATION
// (unitary circuit => sum of probs = 1). RY gates: 2 fma2 per amplitude pair.
// CNOTs: register renames. Epilogue in packed f32x2 + one MUFU reciprocal.
//
// R14: (a) persistent grid + software-pipelined grid-stride loop — next
// iteration's noise LDG.128 issues before this iteration's compute, hiding
// the ~577cyc DRAM latency that previously stalled every wave start;
// (b) product-state init via sign-folded real monomials:
// amp(i) = (-i)^popcount(i) * prod_{w in i} t_w  -> 15 scalar FMULs + 16
// packs-with-zero instead of ~60 packed-mul/mov instructions.
// ============================================================================

typedef unsigned long long u64;

// ---- packed f32x2 helpers (Blackwell sm_100+) ------------------------------

__device__ __forceinline__ u64 pk2(float lo, float hi) {
    u64 r; asm("mov.b64 %0, {%1, %2};" : "=l"(r) : "f"(lo), "f"(hi)); return r;
}
__device__ __forceinline__ void unpk2(u64 v, float& lo, float& hi) {
    asm("mov.b64 {%0, %1}, %2;" : "=f"(lo), "=f"(hi) : "l"(v));
}
__device__ __forceinline__ u64 mul2(u64 a, u64 b) {
    u64 r; asm("mul.rn.f32x2 %0, %1, %2;" : "=l"(r) : "l"(a), "l"(b)); return r;
}
__device__ __forceinline__ u64 add2(u64 a, u64 b) {
    u64 r; asm("add.rn.f32x2 %0, %1, %2;" : "=l"(r) : "l"(a), "l"(b)); return r;
}
__device__ __forceinline__ u64 fma2(u64 a, u64 b, u64 c) {
    u64 r; asm("fma.rn.f32x2 %0, %1, %2, %3;" : "=l"(r) : "l"(a), "l"(b), "l"(c)); return r;
}
__device__ __forceinline__ float hadd2(u64 v) {
    float lo, hi; unpk2(v, lo, hi); return lo + hi;
}

// fast tangent: MUFU sin/cos + MUFU-rcp divide; no slow-path code region
__device__ __forceinline__ float fast_tan_half(float x) {
    float s, c;
    __sincosf(0.5f * x, &s, &c);
    return __fdividef(s, c);
}

// CNOT(ctrl C, tgt T): pure register permutation when fully unrolled.
template <int C, int T>
__device__ __forceinline__ void cnot(u64* a) {
#pragma unroll
    for (int i = 0; i < 16; i++) {
        if ((i & (1 << C)) && !(i & (1 << T))) {
            u64 t = a[i];
            a[i] = a[i | (1 << T)];
            a[i | (1 << T)] = t;
        }
    }
}

__global__ void __launch_bounds__(256, 6)
qc_kernel(const float4* __restrict__ noise,
          const float*  __restrict__ weights,
          float4* __restrict__ out, int n) {
    __shared__ float wt_sh[8];

    // ---- per-block weight tangents: once per block, amortized over loop ----
    if (threadIdx.x < 8) wt_sh[threadIdx.x] = fast_tan_half(weights[threadIdx.x]);
    __syncthreads();

    const int stride = gridDim.x * blockDim.x;
    int b = blockIdx.x * blockDim.x + threadIdx.x;
    if (b >= n) return;

    float4 nz = noise[b];                 // first load (only exposed stall)

    while (true) {
        // ---- software pipeline: issue next iteration's load NOW -----------
        int  bn   = b + stride;
        bool more = bn < n;
        float4 nxt = noise[more ? bn : b];   // unconditional early LDG.128

        // ---- noise tangents (cosines deferred; self-normalizing) ----------
        float t0 = fast_tan_half(nz.x);
        float t1 = fast_tan_half(nz.y);
        float t2 = fast_tan_half(nz.z);
        float t3 = fast_tan_half(nz.w);

        // ---- product state: amp(i) = (-i)^pc(i) * prod_{w in i} t_w -------
        // Sign-folded real monomials g[i] = s_i * m_i, s_i from (-i)^pc.
        float g0 = 1.0f;
        float g1 = -t0;
        float g2 = -t1;
        float g3 =  t1 * g1;
        float g4 = -t2;
        float g5 =  t2 * g1;
        float g6 =  t2 * g2;
        float g7 = -t2 * g3;
        float g8 = -t3;
        float g9 =  t3 * g1;
        float g10 = t3 * g2;
        float g11 = -t3 * g3;
        float g12 = t3 * g4;
        float g13 = -t3 * g5;
        float g14 = -t3 * g6;
        float g15 = t3 * g7;

        // pc even -> pure real, pc odd -> pure imaginary
        u64 a[16];
        a[0]  = pk2(g0, 0.f);  a[1]  = pk2(0.f, g1);
        a[2]  = pk2(0.f, g2);  a[3]  = pk2(g3, 0.f);
        a[4]  = pk2(0.f, g4);  a[5]  = pk2(g5, 0.f);
        a[6]  = pk2(g6, 0.f);  a[7]  = pk2(0.f, g7);
        a[8]  = pk2(0.f, g8);  a[9]  = pk2(g9, 0.f);
        a[10] = pk2(g10, 0.f); a[11] = pk2(0.f, g11);
        a[12] = pk2(g12, 0.f); a[13] = pk2(0.f, g13);
        a[14] = pk2(0.f, g14); a[15] = pk2(g15, 0.f);

        // ---- 2 layers: CNOT ring + RY (deferred cosine: [[1,-t],[t,1]]) ---
#pragma unroll
        for (int layer = 0; layer < 2; layer++) {
            cnot<0, 1>(a);
            cnot<1, 2>(a);
            cnot<2, 3>(a);
            cnot<3, 0>(a);

#pragma unroll
            for (int w = 0; w < 4; w++) {
                float tw = wt_sh[layer * 4 + w];   // LDS broadcast
                u64 tp = pk2(tw, tw);
                u64 tn = pk2(-tw, -tw);
                const int h = 1 << w;
#pragma unroll
                for (int i = 0; i < 16; i++) {
                    if (i & h) continue;
                    u64 a0 = a[i], a1 = a[i | h];
                    a[i]     = fma2(tn, a1, a0);  // a0 - t*a1 (re & im)
                    a[i | h] = fma2(tp, a0, a1);  // a1 + t*a0
                }
            }
        }

        // ---- packed squares + marginals, normalize by total ---------------
        u64 q[16];
#pragma unroll
        for (int i = 0; i < 16; i++) q[i] = mul2(a[i], a[i]);  // (re^2, im^2)

        u64 s01 = add2(q[0],  q[1]),  s23 = add2(q[2],  q[3]);
        u64 s45 = add2(q[4],  q[5]),  s67 = add2(q[6],  q[7]);
        u64 s89 = add2(q[8],  q[9]),  sab = add2(q[10], q[11]);
        u64 scd = add2(q[12], q[13]), sef = add2(q[14], q[15]);

        u64 A = add2(s01, s23);   // q0..q3
        u64 B = add2(s45, s67);   // q4..q7
        u64 C = add2(s89, sab);   // q8..q11
        u64 D = add2(scd, sef);   // q12..q15

        // wire0: even indices
        u64 E = add2(add2(add2(q[0], q[2]), add2(q[4],  q[6])),
                     add2(add2(q[8], q[10]), add2(q[12], q[14])));
        // wire1: {0,1,4,5,8,9,12,13}
        u64 Y = add2(add2(s01, s45), add2(s89, scd));

        u64 AB = add2(A, B);                    // wire 3 numerator
        float T = hadd2(add2(AB, add2(C, D)));  // total probability mass
        float r = __frcp_rn(T);                 // MUFU (pipe is idle)

        float4 o;
        o.x = r * hadd2(E);            // wire 0
        o.y = r * hadd2(Y);            // wire 1
        o.z = r * hadd2(add2(A, C));   // wire 2
        o.w = r * hadd2(AB);           // wire 3

        out[b] = o;

        if (!more) break;
        b  = bn;
        nz = nxt;
    }
}

extern "C" void kernel_launch(void* const* d_in, const int* in_sizes, int n_in,
                              void* d_out, int out_size) {
    const float* noise   = (const float*)d_in[0];   // (B, 4) f32
    const float* weights = (const float*)d_in[1];   // (2, 4) f32
    int B = in_sizes[0] / 4;

    const int threads = 256;
    int blocks = 152 * 6;                            // persistent: 6 CTAs/SM
    int needed = (B + threads - 1) / threads;
    if (blocks > needed) blocks = needed;

    qc_kernel<<<blocks, threads>>>((const float4*)noise, weights,
                                   (float4*)d_out, B);
}

// round 16
// speedup vs baseline: 1.0257x; 1.0240x over previous
#include <cuda_runtime.h>

// ============================================================================
// GeneratorQuantumCircuit: 4-qubit state-vector sim, 1 thread = 1 batch elem.
// State = 16 complex amplitudes packed (re,im) as f32x2 in 64-bit registers.
//
// Tangent (deferred-cosine) gate algebra: every rotation applied as
// [[1,-t],[t,1]]; dropped cosine factors recovered by SELF-NORMALIZATION
// (unitary circuit => sum of probs = 1). RY gates: 2 fma2 per amplitude pair.
// CNOTs: register renames. Epilogue in packed f32x2 + one MUFU reciprocal.
//
// R15: flat grid restored (R14's persistent grid-stride loop caused tail
// imbalance: occ 65->51%, main kernel +1.9us). Kept R14's cheap init:
// amp(i) = (-i)^popcount(i) * prod_{w in i} t_w — 15 scalar FMULs with signs
// folded into operands + zero-packs, replacing the packed-mul build chain.
// ============================================================================

typedef unsigned long long u64;

// ---- packed f32x2 helpers (Blackwell sm_100+) ------------------------------

__device__ __forceinline__ u64 pk2(float lo, float hi) {
    u64 r; asm("mov.b64 %0, {%1, %2};" : "=l"(r) : "f"(lo), "f"(hi)); return r;
}
__device__ __forceinline__ void unpk2(u64 v, float& lo, float& hi) {
    asm("mov.b64 {%0, %1}, %2;" : "=f"(lo), "=f"(hi) : "l"(v));
}
__device__ __forceinline__ u64 mul2(u64 a, u64 b) {
    u64 r; asm("mul.rn.f32x2 %0, %1, %2;" : "=l"(r) : "l"(a), "l"(b)); return r;
}
__device__ __forceinline__ u64 add2(u64 a, u64 b) {
    u64 r; asm("add.rn.f32x2 %0, %1, %2;" : "=l"(r) : "l"(a), "l"(b)); return r;
}
__device__ __forceinline__ u64 fma2(u64 a, u64 b, u64 c) {
    u64 r; asm("fma.rn.f32x2 %0, %1, %2, %3;" : "=l"(r) : "l"(a), "l"(b), "l"(c)); return r;
}
__device__ __forceinline__ float hadd2(u64 v) {
    float lo, hi; unpk2(v, lo, hi); return lo + hi;
}

// fast tangent: MUFU sin/cos + MUFU-rcp divide; no slow-path code region
__device__ __forceinline__ float fast_tan_half(float x) {
    float s, c;
    __sincosf(0.5f * x, &s, &c);
    return __fdividef(s, c);
}

// CNOT(ctrl C, tgt T): pure register permutation when fully unrolled.
template <int C, int T>
__device__ __forceinline__ void cnot(u64* a) {
#pragma unroll
    for (int i = 0; i < 16; i++) {
        if ((i & (1 << C)) && !(i & (1 << T))) {
            u64 t = a[i];
            a[i] = a[i | (1 << T)];
            a[i | (1 << T)] = t;
        }
    }
}

__global__ void __launch_bounds__(256, 6)
qc_kernel(const float4* __restrict__ noise,
          const float*  __restrict__ weights,
          float4* __restrict__ out, int n) {
    __shared__ float wt_sh[8];

    // ---- per-block weight tangents: 8 fast-math tans, once per block -------
    if (threadIdx.x < 8) wt_sh[threadIdx.x] = fast_tan_half(weights[threadIdx.x]);
    __syncthreads();

    int b = blockIdx.x * blockDim.x + threadIdx.x;
    if (b >= n) return;

    float wt[8];
#pragma unroll
    for (int i = 0; i < 8; i++) wt[i] = wt_sh[i];   // LDS broadcast, N=1

    // ---- noise tangents (cosines deferred; self-normalizing) ---------------
    float4 nz = noise[b];
    float t0 = fast_tan_half(nz.x);
    float t1 = fast_tan_half(nz.y);
    float t2 = fast_tan_half(nz.z);
    float t3 = fast_tan_half(nz.w);

    // ---- product state: amp(i) = (-i)^popcount(i) * prod_{w in i} t_w ------
    // Sign-folded real monomials; popcount even -> pure real, odd -> pure imag.
    float g0 = 1.0f;
    float g1 = -t0;
    float g2 = -t1;
    float g3 =  t1 * g1;
    float g4 = -t2;
    float g5 =  t2 * g1;
    float g6 =  t2 * g2;
    float g7 = -t2 * g3;
    float g8 = -t3;
    float g9 =  t3 * g1;
    float g10 = t3 * g2;
    float g11 = -t3 * g3;
    float g12 = t3 * g4;
    float g13 = -t3 * g5;
    float g14 = -t3 * g6;
    float g15 = t3 * g7;

    u64 a[16];
    a[0]  = pk2(g0, 0.f);  a[1]  = pk2(0.f, g1);
    a[2]  = pk2(0.f, g2);  a[3]  = pk2(g3, 0.f);
    a[4]  = pk2(0.f, g4);  a[5]  = pk2(g5, 0.f);
    a[6]  = pk2(g6, 0.f);  a[7]  = pk2(0.f, g7);
    a[8]  = pk2(0.f, g8);  a[9]  = pk2(g9, 0.f);
    a[10] = pk2(g10, 0.f); a[11] = pk2(0.f, g11);
    a[12] = pk2(g12, 0.f); a[13] = pk2(0.f, g13);
    a[14] = pk2(0.f, g14); a[15] = pk2(g15, 0.f);

    // ---- 2 layers: CNOT ring + RY (deferred cosine: [[1,-t],[t,1]]) --------
#pragma unroll
    for (int layer = 0; layer < 2; layer++) {
        cnot<0, 1>(a);
        cnot<1, 2>(a);
        cnot<2, 3>(a);
        cnot<3, 0>(a);

#pragma unroll
        for (int w = 0; w < 4; w++) {
            float tw = wt[layer * 4 + w];
            u64 tp = pk2(tw, tw);
            u64 tn = pk2(-tw, -tw);
            const int h = 1 << w;
#pragma unroll
            for (int i = 0; i < 16; i++) {
                if (i & h) continue;
                u64 a0 = a[i], a1 = a[i | h];
                a[i]     = fma2(tn, a1, a0);  // a0 - t*a1  (re & im together)
                a[i | h] = fma2(tp, a0, a1);  // a1 + t*a0
            }
        }
    }

    // ---- packed squares + marginals, then normalize by total ---------------
    u64 q[16];
#pragma unroll
    for (int i = 0; i < 16; i++) q[i] = mul2(a[i], a[i]);  // (re^2, im^2)

    u64 s01 = add2(q[0],  q[1]),  s23 = add2(q[2],  q[3]);
    u64 s45 = add2(q[4],  q[5]),  s67 = add2(q[6],  q[7]);
    u64 s89 = add2(q[8],  q[9]),  sab = add2(q[10], q[11]);
    u64 scd = add2(q[12], q[13]), sef = add2(q[14], q[15]);

    u64 A = add2(s01, s23);   // q0..q3
    u64 B = add2(s45, s67);   // q4..q7
    u64 C = add2(s89, sab);   // q8..q11
    u64 D = add2(scd, sef);   // q12..q15

    // wire0: even indices
    u64 E = add2(add2(add2(q[0], q[2]), add2(q[4],  q[6])),
                 add2(add2(q[8], q[10]), add2(q[12], q[14])));
    // wire1: {0,1,4,5,8,9,12,13}
    u64 Y = add2(add2(s01, s45), add2(s89, scd));

    u64 AB = add2(A, B);                    // wire 3 numerator (and half of T)
    float T = hadd2(add2(AB, add2(C, D)));  // total probability mass
    float r = __frcp_rn(T);                 // MUFU reciprocal (pipe is idle)

    float4 o;
    o.x = r * hadd2(E);            // wire 0
    o.y = r * hadd2(Y);            // wire 1
    o.z = r * hadd2(add2(A, C));   // wire 2
    o.w = r * hadd2(AB);           // wire 3

    out[b] = o;
}

extern "C" void kernel_launch(void* const* d_in, const int* in_sizes, int n_in,
                              void* d_out, int out_size) {
    const float* noise   = (const float*)d_in[0];   // (B, 4) f32
    const float* weights = (const float*)d_in[1];   // (2, 4) f32
    int B = in_sizes[0] / 4;

    int threads = 256;
    int blocks = (B + threads - 1) / threads;
    qc_kernel<<<blocks, threads>>>((const float4*)noise, weights,
                                   (float4*)d_out, B);
}